// round 1
// baseline (speedup 1.0000x reference)
#include <cuda_runtime.h>

// Problem shape (fixed by the benchmark dataset)
#define BATCH 8
#define NPTS  2048
#define CIN   64
#define COUT  64
#define NW    (NPTS / 32)   // 64 mask words per (z,a) row

// Scratch: static device globals (no allocation allowed in kernel_launch)
__device__ unsigned g_mask[BATCH * NPTS * NW];  // 4 MB bitmask: bit set -> neighbor
__device__ float4   g_g4[BATCH * NPTS];         // padded geometry for aligned 16B loads

// ---------------------------------------------------------------------------
// Kernel 1: pack geometry [z, b, 3] -> float4 (x, y, z, 0)
// ---------------------------------------------------------------------------
__global__ void pack_geom_kernel(const float* __restrict__ geom) {
    int p = blockIdx.x * blockDim.x + threadIdx.x;
    if (p < BATCH * NPTS) {
        float gx = geom[3 * p + 0];
        float gy = geom[3 * p + 1];
        float gz = geom[3 * p + 2];
        g_g4[p] = make_float4(gx, gy, gz, 0.0f);
    }
}

// ---------------------------------------------------------------------------
// Kernel 2: build neighbor bitmask.  bit t of word (z,a,w) <-> b = w*32+t,
// set iff ||g_b - g_a||^2 < 1.  (sqrt monotone, so norm<1 <=> norm^2<1)
// Block: 256 threads = 4 a's x 64 words.
// ---------------------------------------------------------------------------
__global__ void build_mask_kernel() {
    int z = blockIdx.y;
    int a = blockIdx.x * 4 + (threadIdx.x >> 6);
    int w = threadIdx.x & 63;

    float4 ga = g_g4[z * NPTS + a];
    const float4* gb_base = &g_g4[z * NPTS + w * 32];

    unsigned word = 0;
#pragma unroll 8
    for (int t = 0; t < 32; t++) {
        float4 gb = gb_base[t];
        float dx = gb.x - ga.x;
        float dy = gb.y - ga.y;
        float dz = gb.z - ga.z;
        float n2 = fmaf(dx, dx, fmaf(dy, dy, dz * dz));
        if (n2 < 1.0f) word |= (1u << t);
    }
    g_mask[(z * NPTS + a) * NW + w] = word;
}

// ---------------------------------------------------------------------------
// Kernel 3: main convolution.
// One warp owns one output point a.  Each lane owns j = {2*lane, 2*lane+1}.
// Accumulate A0[j] = sum_b m f[b,j], A1[x,j] = sum_b m g_b[x] f[b,j]
// over set bits only (mask is warp-uniform -> no divergence).
// Then s[x,j] = A1[x,j] - g_a[x]*A0[j], and fused epilogue
// out[a,i] = sum_{x,j} s[x,j] * Wk[x,i,j]  (N_NORM = 1 -> no scaling).
// Block: 256 threads = 8 warps = 8 a's.
// ---------------------------------------------------------------------------
__global__ void conv_main_kernel(const float* __restrict__ feat,
                                 const float* __restrict__ Wk,
                                 float* __restrict__ out) {
    const int z    = blockIdx.y;
    const int wid  = threadIdx.x >> 5;
    const int lane = threadIdx.x & 31;
    const int a    = blockIdx.x * 8 + wid;

    const float2* __restrict__ fz =
        reinterpret_cast<const float2*>(feat + (size_t)z * NPTS * CIN);
    const unsigned* __restrict__ mrow = g_mask + ((size_t)z * NPTS + a) * NW;
    const float4* __restrict__ g4z = g_g4 + (size_t)z * NPTS;

    float a00 = 0.f, a01 = 0.f;             // A0
    float ax0 = 0.f, ax1 = 0.f;             // A1 x
    float ay0 = 0.f, ay1 = 0.f;             // A1 y
    float az0 = 0.f, az1 = 0.f;             // A1 z

#pragma unroll 1
    for (int w = 0; w < NW; w++) {
        unsigned m = mrow[w];
        const int b32 = w * 32;
        while (m) {
            const int t = __ffs(m) - 1;
            m &= (m - 1);
            const int b = b32 + t;
            const float4 gb = g4z[b];
            const float2 f  = fz[b * 32 + lane];   // j = 2*lane, 2*lane+1
            a00 += f.x;                a01 += f.y;
            ax0 = fmaf(gb.x, f.x, ax0); ax1 = fmaf(gb.x, f.y, ax1);
            ay0 = fmaf(gb.y, f.x, ay0); ay1 = fmaf(gb.y, f.y, ay1);
            az0 = fmaf(gb.z, f.x, az0); az1 = fmaf(gb.z, f.y, az1);
        }
    }

    // s[x,j] = A1[x,j] - g_a[x] * A0[j]
    const float4 ga = g4z[a];
    __shared__ float s_s[8][3 * 64];   // per-warp s tile (16B-aligned rows)
    const int j0 = 2 * lane;
    s_s[wid][0 * 64 + j0]     = fmaf(-ga.x, a00, ax0);
    s_s[wid][0 * 64 + j0 + 1] = fmaf(-ga.x, a01, ax1);
    s_s[wid][1 * 64 + j0]     = fmaf(-ga.y, a00, ay0);
    s_s[wid][1 * 64 + j0 + 1] = fmaf(-ga.y, a01, ay1);
    s_s[wid][2 * 64 + j0]     = fmaf(-ga.z, a00, az0);
    s_s[wid][2 * 64 + j0 + 1] = fmaf(-ga.z, a01, az1);
    __syncwarp();

    // Epilogue: each lane produces i0 = lane, i1 = lane+32.
    // Wk rows are contiguous in j -> float4 loads; s broadcast via LDS.128.
    const int i0 = lane, i1 = lane + 32;
    float o0 = 0.f, o1 = 0.f;
#pragma unroll
    for (int x = 0; x < 3; x++) {
        const float4* __restrict__ w0 =
            reinterpret_cast<const float4*>(Wk + x * COUT * CIN + i0 * CIN);
        const float4* __restrict__ w1 =
            reinterpret_cast<const float4*>(Wk + x * COUT * CIN + i1 * CIN);
        const float4* __restrict__ s4 =
            reinterpret_cast<const float4*>(&s_s[wid][x * 64]);
#pragma unroll
        for (int q = 0; q < 16; q++) {
            const float4 s  = s4[q];
            const float4 wa = w0[q];
            const float4 wb = w1[q];
            o0 = fmaf(s.x, wa.x, o0); o0 = fmaf(s.y, wa.y, o0);
            o0 = fmaf(s.z, wa.z, o0); o0 = fmaf(s.w, wa.w, o0);
            o1 = fmaf(s.x, wb.x, o1); o1 = fmaf(s.y, wb.y, o1);
            o1 = fmaf(s.z, wb.z, o1); o1 = fmaf(s.w, wb.w, o1);
        }
    }

    float* __restrict__ orow = out + ((size_t)z * NPTS + a) * COUT;
    orow[i0] = o0;
    orow[i1] = o1;
}

// ---------------------------------------------------------------------------
// Launcher.  Inputs (metadata order): features [8,2048,64] f32,
// geometry [8,2048,3] f32, Wk [3,64,64] f32.  Output [8,2048,64] f32.
// All launches on the default (capture) stream; no sync, no allocation.
// ---------------------------------------------------------------------------
extern "C" void kernel_launch(void* const* d_in, const int* in_sizes, int n_in,
                              void* d_out, int out_size) {
    const float* feat = (const float*)d_in[0];
    const float* geom = (const float*)d_in[1];
    const float* Wk   = (const float*)d_in[2];
    float* out = (float*)d_out;

    (void)in_sizes; (void)n_in; (void)out_size;

    // 1) pack geometry into float4
    pack_geom_kernel<<<(BATCH * NPTS + 255) / 256, 256>>>(geom);

    // 2) bitmask: grid (NPTS/4, BATCH), 256 threads (4 a's x 64 words)
    {
        dim3 grid(NPTS / 4, BATCH);
        build_mask_kernel<<<grid, 256>>>();
    }

    // 3) main conv: grid (NPTS/8, BATCH), 256 threads = 8 warps = 8 a's
    {
        dim3 grid(NPTS / 8, BATCH);
        conv_main_kernel<<<grid, 256>>>(feat, Wk, out);
    }
}

// round 2
// speedup vs baseline: 1.4548x; 1.4548x over previous
#include <cuda_runtime.h>

// Problem shape (fixed by the benchmark dataset)
#define BATCH 8
#define NPTS  2048
#define CIN   64
#define COUT  64
#define WARPS 8                       // a's per block
#define CHUNK_WORDS 16                // 16 mask words = 512 b's per chunk
#define CHUNK_B (CHUNK_WORDS * 32)

// ---------------------------------------------------------------------------
// Single fused kernel.
// One warp owns one output point a. For each 512-b chunk:
//   build phase: lanes test ||g_b - g_a||^2 < 1, ballot -> compact neighbor
//                index list in smem (warp-synchronous prefix via popc).
//   consume:     4 neighbors per iteration -> 4 independent f gathers + 4
//                uniform geometry loads in flight (MLP>=4).
// Accumulators: A0[j] = sum_b f[b,j], A1[x,j] = sum_b g_b[x] f[b,j]
// (each lane owns j = 2*lane, 2*lane+1). Then s = A1 - g_a*A0 and the fused
// Wk epilogue: out[a,i] = sum_{x,j} s[x,j] Wk[x,i,j].  (N_NORM=1.)
// Self-term b=a cancels exactly in the A1 - g_a*A0 form.
// ---------------------------------------------------------------------------
__global__ __launch_bounds__(WARPS * 32) void conv_fused_kernel(
    const float* __restrict__ feat,
    const float* __restrict__ geom,
    const float* __restrict__ Wk,
    float* __restrict__ out)
{
    const int z    = blockIdx.y;
    const int wid  = threadIdx.x >> 5;
    const int lane = threadIdx.x & 31;
    const int a    = blockIdx.x * WARPS + wid;

    const float2* __restrict__ fz = reinterpret_cast<const float2*>(
        feat + (size_t)z * NPTS * CIN);
    const float* __restrict__ gz = geom + (size_t)z * NPTS * 3;

    __shared__ unsigned short s_list[WARPS][CHUNK_B];  // 8 KB
    __shared__ float s_s[WARPS][3 * 64];               // 6 KB

    const float gax = gz[3 * a + 0];
    const float gay = gz[3 * a + 1];
    const float gaz = gz[3 * a + 2];

    float a00 = 0.f, a01 = 0.f;   // A0
    float ax0 = 0.f, ax1 = 0.f;   // A1.x
    float ay0 = 0.f, ay1 = 0.f;   // A1.y
    float az0 = 0.f, az1 = 0.f;   // A1.z

#pragma unroll 1
    for (int c = 0; c < NPTS / CHUNK_B; c++) {
        const int base = c * CHUNK_B;

        // ---- build neighbor list for this chunk (warp-synchronous) ----
        int cnt = 0;
#pragma unroll
        for (int w = 0; w < CHUNK_WORDS; w++) {
            const int b = base + w * 32 + lane;
            const float dx = gz[3 * b + 0] - gax;
            const float dy = gz[3 * b + 1] - gay;
            const float dz = gz[3 * b + 2] - gaz;
            const float n2 = fmaf(dx, dx, fmaf(dy, dy, dz * dz));
            const bool hit = (n2 < 1.0f);
            const unsigned m = __ballot_sync(0xffffffffu, hit);
            if (hit) {
                const int pos = cnt + __popc(m & ((1u << lane) - 1u));
                s_list[wid][pos] = (unsigned short)b;
            }
            cnt += __popc(m);
        }
        __syncwarp();

        // ---- consume: 4 neighbors per iteration (MLP >= 4) ----
        int k = 0;
        for (; k + 4 <= cnt; k += 4) {
            const ushort4 bb = *reinterpret_cast<const ushort4*>(&s_list[wid][k]);
            const int b0 = bb.x, b1 = bb.y, b2 = bb.z, b3 = bb.w;

            // 4 independent feature gathers (coalesced 256B per warp each)
            const float2 f0 = fz[b0 * (CIN / 2) + lane];
            const float2 f1 = fz[b1 * (CIN / 2) + lane];
            const float2 f2 = fz[b2 * (CIN / 2) + lane];
            const float2 f3 = fz[b3 * (CIN / 2) + lane];

            // warp-uniform geometry broadcasts (L1-resident)
            const float g0x = gz[3 * b0], g0y = gz[3 * b0 + 1], g0z = gz[3 * b0 + 2];
            const float g1x = gz[3 * b1], g1y = gz[3 * b1 + 1], g1z = gz[3 * b1 + 2];
            const float g2x = gz[3 * b2], g2y = gz[3 * b2 + 1], g2z = gz[3 * b2 + 2];
            const float g3x = gz[3 * b3], g3y = gz[3 * b3 + 1], g3z = gz[3 * b3 + 2];

            a00 += f0.x; a01 += f0.y;
            ax0 = fmaf(g0x, f0.x, ax0); ax1 = fmaf(g0x, f0.y, ax1);
            ay0 = fmaf(g0y, f0.x, ay0); ay1 = fmaf(g0y, f0.y, ay1);
            az0 = fmaf(g0z, f0.x, az0); az1 = fmaf(g0z, f0.y, az1);

            a00 += f1.x; a01 += f1.y;
            ax0 = fmaf(g1x, f1.x, ax0); ax1 = fmaf(g1x, f1.y, ax1);
            ay0 = fmaf(g1y, f1.x, ay0); ay1 = fmaf(g1y, f1.y, ay1);
            az0 = fmaf(g1z, f1.x, az0); az1 = fmaf(g1z, f1.y, az1);

            a00 += f2.x; a01 += f2.y;
            ax0 = fmaf(g2x, f2.x, ax0); ax1 = fmaf(g2x, f2.y, ax1);
            ay0 = fmaf(g2y, f2.x, ay0); ay1 = fmaf(g2y, f2.y, ay1);
            az0 = fmaf(g2z, f2.x, az0); az1 = fmaf(g2z, f2.y, az1);

            a00 += f3.x; a01 += f3.y;
            ax0 = fmaf(g3x, f3.x, ax0); ax1 = fmaf(g3x, f3.y, ax1);
            ay0 = fmaf(g3y, f3.x, ay0); ay1 = fmaf(g3y, f3.y, ay1);
            az0 = fmaf(g3z, f3.x, az0); az1 = fmaf(g3z, f3.y, az1);
        }
        for (; k < cnt; k++) {
            const int b = s_list[wid][k];
            const float2 f = fz[b * (CIN / 2) + lane];
            const float gbx = gz[3 * b], gby = gz[3 * b + 1], gbz = gz[3 * b + 2];
            a00 += f.x; a01 += f.y;
            ax0 = fmaf(gbx, f.x, ax0); ax1 = fmaf(gbx, f.y, ax1);
            ay0 = fmaf(gby, f.x, ay0); ay1 = fmaf(gby, f.y, ay1);
            az0 = fmaf(gbz, f.x, az0); az1 = fmaf(gbz, f.y, az1);
        }
        __syncwarp();
    }

    // ---- s[x,j] = A1[x,j] - g_a[x] * A0[j] ----
    const int j0 = 2 * lane;
    s_s[wid][0 * 64 + j0]     = fmaf(-gax, a00, ax0);
    s_s[wid][0 * 64 + j0 + 1] = fmaf(-gax, a01, ax1);
    s_s[wid][1 * 64 + j0]     = fmaf(-gay, a00, ay0);
    s_s[wid][1 * 64 + j0 + 1] = fmaf(-gay, a01, ay1);
    s_s[wid][2 * 64 + j0]     = fmaf(-gaz, a00, az0);
    s_s[wid][2 * 64 + j0 + 1] = fmaf(-gaz, a01, az1);
    __syncwarp();

    // ---- fused epilogue: out[a,i] = sum_{x,j} s[x,j] * Wk[x,i,j] ----
    const int i0 = lane, i1 = lane + 32;
    float o0 = 0.f, o1 = 0.f;
#pragma unroll
    for (int x = 0; x < 3; x++) {
        const float4* __restrict__ w0 =
            reinterpret_cast<const float4*>(Wk + x * COUT * CIN + i0 * CIN);
        const float4* __restrict__ w1 =
            reinterpret_cast<const float4*>(Wk + x * COUT * CIN + i1 * CIN);
        const float4* __restrict__ s4 =
            reinterpret_cast<const float4*>(&s_s[wid][x * 64]);
#pragma unroll
        for (int q = 0; q < 16; q++) {
            const float4 s  = s4[q];   // warp-uniform broadcast
            const float4 wa = w0[q];
            const float4 wb = w1[q];
            o0 = fmaf(s.x, wa.x, o0); o0 = fmaf(s.y, wa.y, o0);
            o0 = fmaf(s.z, wa.z, o0); o0 = fmaf(s.w, wa.w, o0);
            o1 = fmaf(s.x, wb.x, o1); o1 = fmaf(s.y, wb.y, o1);
            o1 = fmaf(s.z, wb.z, o1); o1 = fmaf(s.w, wb.w, o1);
        }
    }

    float* __restrict__ orow = out + ((size_t)z * NPTS + a) * COUT;
    orow[i0] = o0;
    orow[i1] = o1;
}

// ---------------------------------------------------------------------------
// Launcher. Inputs (metadata order): features [8,2048,64] f32,
// geometry [8,2048,3] f32, Wk [3,64,64] f32. Output [8,2048,64] f32.
// Single launch -> ncu -s 5 -c 1 is guaranteed to profile this kernel.
// ---------------------------------------------------------------------------
extern "C" void kernel_launch(void* const* d_in, const int* in_sizes, int n_in,
                              void* d_out, int out_size) {
    const float* feat = (const float*)d_in[0];
    const float* geom = (const float*)d_in[1];
    const float* Wk   = (const float*)d_in[2];
    float* out = (float*)d_out;

    (void)in_sizes; (void)n_in; (void)out_size;

    dim3 grid(NPTS / WARPS, BATCH);
    conv_fused_kernel<<<grid, WARPS * 32>>>(feat, geom, Wk, out);
}

// round 3
// speedup vs baseline: 2.0975x; 1.4418x over previous
#include <cuda_runtime.h>

// Problem shape (fixed by the benchmark dataset)
#define BATCH 8
#define NPTS  2048
#define CIN   64
#define COUT  64
#define WARPS 8                       // a's per block
#define CHUNK_WORDS 16                // 16 ballots = 512 b's per chunk
#define CHUNK_B (CHUNK_WORDS * 32)
#define SROW   196                    // padded s row (floats): 4*a % 32 banks distinct

// ---------------------------------------------------------------------------
// Single fused kernel. One warp owns one output point a for the accumulation;
// the epilogue is block-cooperative (warp w owns 8 output channels i for all
// 8 a's of the block) so Wk is read with 4-distinct-address (cheap) loads.
//
// Accumulators: A0[j] = sum_b m f[b,j], A1[x,j] = sum_b m g_b[x] f[b,j]
// (lane owns j = 2*lane, 2*lane+1). s = A1 - g_a*A0 (b=a self-term cancels),
// out[a,i] = sum_{x,j} s[x,j] Wk[x,i,j].  N_NORM = 1 -> no scaling.
// ---------------------------------------------------------------------------
__global__ __launch_bounds__(WARPS * 32) void conv_fused_kernel(
    const float* __restrict__ feat,
    const float* __restrict__ geom,
    const float* __restrict__ Wk,
    float* __restrict__ out)
{
    const int z    = blockIdx.y;
    const int tid  = threadIdx.x;
    const int wid  = tid >> 5;
    const int lane = tid & 31;
    const int a0blk = blockIdx.x * WARPS;
    const int a    = a0blk + wid;

    const float2* __restrict__ fz = reinterpret_cast<const float2*>(
        feat + (size_t)z * NPTS * CIN);
    const float* __restrict__ gz = geom + (size_t)z * NPTS * 3;

    __shared__ float4        s_g4[NPTS];                 // 32 KB geometry (xyz_)
    __shared__ unsigned short s_list[WARPS][CHUNK_B];    // 8 KB neighbor lists
    __shared__ float         s_s[WARPS][SROW];           // 6.1 KB s tiles

    // ---- stage geometry into smem (coalesced gmem reads) ----
    {
        float* s_graw = reinterpret_cast<float*>(s_g4);
        for (int t = tid; t < NPTS * 3; t += WARPS * 32) {
            s_graw[(t / 3) * 4 + (t % 3)] = gz[t];
        }
    }
    __syncthreads();

    const float4 ga = s_g4[a];

    float a00 = 0.f, a01 = 0.f;   // A0
    float ax0 = 0.f, ax1 = 0.f;   // A1.x
    float ay0 = 0.f, ay1 = 0.f;   // A1.y
    float az0 = 0.f, az1 = 0.f;   // A1.z

#pragma unroll 1
    for (int c = 0; c < NPTS / CHUNK_B; c++) {
        const int base = c * CHUNK_B;

        // ---- build neighbor list for this chunk (warp-synchronous) ----
        int cnt = 0;
#pragma unroll
        for (int w = 0; w < CHUNK_WORDS; w++) {
            const int b = base + w * 32 + lane;
            const float4 gb = s_g4[b];                 // conflict-free LDS.128
            const float dx = gb.x - ga.x;
            const float dy = gb.y - ga.y;
            const float dz = gb.z - ga.z;
            const float n2 = fmaf(dx, dx, fmaf(dy, dy, dz * dz));
            const bool hit = (n2 < 1.0f);
            const unsigned m = __ballot_sync(0xffffffffu, hit);
            if (hit) {
                const int pos = cnt + __popc(m & ((1u << lane) - 1u));
                s_list[wid][pos] = (unsigned short)b;
            }
            cnt += __popc(m);
        }
        __syncwarp();

        // ---- consume: 4 neighbors per iteration (MLP >= 4) ----
        int k = 0;
        for (; k + 4 <= cnt; k += 4) {
            const ushort4 bb = *reinterpret_cast<const ushort4*>(&s_list[wid][k]);
            const int b0 = bb.x, b1 = bb.y, b2 = bb.z, b3 = bb.w;

            // 4 independent feature gathers (coalesced 256B per warp each)
            const float2 f0 = fz[b0 * (CIN / 2) + lane];
            const float2 f1 = fz[b1 * (CIN / 2) + lane];
            const float2 f2 = fz[b2 * (CIN / 2) + lane];
            const float2 f3 = fz[b3 * (CIN / 2) + lane];

            // warp-uniform 16B smem broadcasts (1 phase each)
            const float4 g0 = s_g4[b0];
            const float4 g1 = s_g4[b1];
            const float4 g2 = s_g4[b2];
            const float4 g3 = s_g4[b3];

            a00 += f0.x; a01 += f0.y;
            ax0 = fmaf(g0.x, f0.x, ax0); ax1 = fmaf(g0.x, f0.y, ax1);
            ay0 = fmaf(g0.y, f0.x, ay0); ay1 = fmaf(g0.y, f0.y, ay1);
            az0 = fmaf(g0.z, f0.x, az0); az1 = fmaf(g0.z, f0.y, az1);

            a00 += f1.x; a01 += f1.y;
            ax0 = fmaf(g1.x, f1.x, ax0); ax1 = fmaf(g1.x, f1.y, ax1);
            ay0 = fmaf(g1.y, f1.x, ay0); ay1 = fmaf(g1.y, f1.y, ay1);
            az0 = fmaf(g1.z, f1.x, az0); az1 = fmaf(g1.z, f1.y, az1);

            a00 += f2.x; a01 += f2.y;
            ax0 = fmaf(g2.x, f2.x, ax0); ax1 = fmaf(g2.x, f2.y, ax1);
            ay0 = fmaf(g2.y, f2.x, ay0); ay1 = fmaf(g2.y, f2.y, ay1);
            az0 = fmaf(g2.z, f2.x, az0); az1 = fmaf(g2.z, f2.y, az1);

            a00 += f3.x; a01 += f3.y;
            ax0 = fmaf(g3.x, f3.x, ax0); ax1 = fmaf(g3.x, f3.y, ax1);
            ay0 = fmaf(g3.y, f3.x, ay0); ay1 = fmaf(g3.y, f3.y, ay1);
            az0 = fmaf(g3.z, f3.x, az0); az1 = fmaf(g3.z, f3.y, az1);
        }
        for (; k < cnt; k++) {
            const int b = s_list[wid][k];
            const float2 f = fz[b * (CIN / 2) + lane];
            const float4 gb = s_g4[b];
            a00 += f.x; a01 += f.y;
            ax0 = fmaf(gb.x, f.x, ax0); ax1 = fmaf(gb.x, f.y, ax1);
            ay0 = fmaf(gb.y, f.x, ay0); ay1 = fmaf(gb.y, f.y, ay1);
            az0 = fmaf(gb.z, f.x, az0); az1 = fmaf(gb.z, f.y, az1);
        }
        __syncwarp();
    }

    // ---- s[x,j] = A1[x,j] - g_a[x] * A0[j] ----
    const int j0 = 2 * lane;
    s_s[wid][0 * 64 + j0]     = fmaf(-ga.x, a00, ax0);
    s_s[wid][0 * 64 + j0 + 1] = fmaf(-ga.x, a01, ax1);
    s_s[wid][1 * 64 + j0]     = fmaf(-ga.y, a00, ay0);
    s_s[wid][1 * 64 + j0 + 1] = fmaf(-ga.y, a01, ay1);
    s_s[wid][2 * 64 + j0]     = fmaf(-ga.z, a00, az0);
    s_s[wid][2 * 64 + j0 + 1] = fmaf(-ga.z, a01, az1);
    __syncthreads();   // epilogue is block-cooperative: all warps read all s rows

    // ---- block-cooperative epilogue ----
    // lane -> (aw = lane/4, q = lane&3); warp w computes i0 = 8w+q, i1 = 8w+q+4
    // for point a0blk+aw.  Wk loads: only 4 distinct 16B addresses per warp
    // (~1 wavefront); s loads: 8 distinct padded rows -> conflict-free LDS.128.
    const int aw = lane >> 2;
    const int q  = lane & 3;
    const int i0 = wid * 8 + q;
    const int i1 = i0 + 4;

    float o0 = 0.f, o1 = 0.f;
#pragma unroll
    for (int x = 0; x < 3; x++) {
        const float4* __restrict__ w0 =
            reinterpret_cast<const float4*>(Wk + (x * COUT + i0) * CIN);
        const float4* __restrict__ w1 =
            reinterpret_cast<const float4*>(Wk + (x * COUT + i1) * CIN);
        const float4* __restrict__ s4 =
            reinterpret_cast<const float4*>(&s_s[aw][x * 64]);
#pragma unroll
        for (int p = 0; p < 16; p++) {
            const float4 s  = s4[p];
            const float4 wa = w0[p];
            const float4 wb = w1[p];
            o0 = fmaf(s.x, wa.x, o0); o0 = fmaf(s.y, wa.y, o0);
            o0 = fmaf(s.z, wa.z, o0); o0 = fmaf(s.w, wa.w, o0);
            o1 = fmaf(s.x, wb.x, o1); o1 = fmaf(s.y, wb.y, o1);
            o1 = fmaf(s.z, wb.z, o1); o1 = fmaf(s.w, wb.w, o1);
        }
    }

    float* __restrict__ orow = out + ((size_t)z * NPTS + a0blk + aw) * COUT;
    orow[i0] = o0;
    orow[i1] = o1;
}

// ---------------------------------------------------------------------------
// Launcher. Inputs (metadata order): features [8,2048,64] f32,
// geometry [8,2048,3] f32, Wk [3,64,64] f32. Output [8,2048,64] f32.
// ---------------------------------------------------------------------------
extern "C" void kernel_launch(void* const* d_in, const int* in_sizes, int n_in,
                              void* d_out, int out_size) {
    const float* feat = (const float*)d_in[0];
    const float* geom = (const float*)d_in[1];
    const float* Wk   = (const float*)d_in[2];
    float* out = (float*)d_out;

    (void)in_sizes; (void)n_in; (void)out_size;

    dim3 grid(NPTS / WARPS, BATCH);
    conv_fused_kernel<<<grid, WARPS * 32>>>(feat, geom, Wk, out);
}

// round 5
// speedup vs baseline: 2.1614x; 1.0304x over previous
#include <cuda_runtime.h>
#include <cuda_bf16.h>
#include <cstdint>

#define BATCH 8
#define NPTS  2048
#define CIN   64
#define NE    192            // e rows (3*64)
#define NIP   256            // H width: [c(64) | e(192)]
#define MT    128            // a-rows per CTA
#define KC    64             // K chunk (b's)
#define NCHUNK (NPTS / KC)
#define THREADS 512

// Static device scratch (allocation is forbidden)
__device__ float g_E[(size_t)BATCH * NE * NPTS];                       // [z][i''][b]
__device__ __align__(128) __nv_bfloat16 g_H[(size_t)2 * BATCH * NIP * NPTS]; // [s][z][i'][b]

// ---------------- smem layout (dynamic, byte offsets) ----------------
#define A_ROWB   144u                       // A row stride bytes (64 bf16 + pad)
#define A_STAGE  (MT * A_ROWB)              // 18432
#define A_OFF    0u                         // 2 stages: 36864
#define B_ROWB   144u
#define B_SPLIT  (NIP * B_ROWB)             // 36864
#define B_STAGE  (2u * B_SPLIT)             // 73728 (hi+lo)
#define B_OFF    36864u                     // 2 stages: 147456 -> end 184320
#define GBP_OFF  184320u                    // packed gb, 2 stages x 1024
#define GBQ_OFF  186368u                    // float4 gb (swizzled), 1088
#define GA_OFF   187456u                    // 128 x float4
#define SMEM_BYTES (GA_OFF + 2048u)         // 189504

__device__ __forceinline__ uint32_t smem_u32(const void* p) {
    uint32_t a;
    asm("{ .reg .u64 t; cvta.to.shared.u64 t, %1; cvt.u32.u64 %0, t; }" : "=r"(a) : "l"(p));
    return a;
}
__device__ __forceinline__ void cpasync16(uint32_t dst, const void* src) {
    asm volatile("cp.async.cg.shared.global [%0], [%1], 16;" :: "r"(dst), "l"(src) : "memory");
}
__device__ __forceinline__ void mma16816(float& d0, float& d1, float& d2, float& d3,
                                         uint32_t a0, uint32_t a1, uint32_t a2, uint32_t a3,
                                         uint32_t b0, uint32_t b1) {
    asm volatile(
        "mma.sync.aligned.m16n8k16.row.col.f32.bf16.bf16.f32 "
        "{%0,%1,%2,%3}, {%4,%5,%6,%7}, {%8,%9}, {%0,%1,%2,%3};"
        : "+f"(d0), "+f"(d1), "+f"(d2), "+f"(d3)
        : "r"(a0), "r"(a1), "r"(a2), "r"(a3), "r"(b0), "r"(b1));
}

// ---------------------------------------------------------------------------
// Prep 1: E[z][i''][b] = sum_j feat[z][b][j] * Wk[x][i][j], i'' = 64x + i
// ---------------------------------------------------------------------------
__global__ __launch_bounds__(256) void prep_e_kernel(const float* __restrict__ feat,
                                                     const float* __restrict__ Wk) {
    __shared__ float s_wk[3 * 64 * 64];   // 48 KB
    const int z  = blockIdx.y;
    const int b0 = blockIdx.x * 64;
    const int t  = threadIdx.x;
    for (int m = t; m < 3 * 64 * 64 / 4; m += 256)
        reinterpret_cast<float4*>(s_wk)[m] = reinterpret_cast<const float4*>(Wk)[m];

    const int bl = t & 63, q = t >> 6;
    const int b = b0 + bl;
    float4 fr[16];
    const float4* fp = reinterpret_cast<const float4*>(feat + ((size_t)z * NPTS + b) * CIN);
#pragma unroll
    for (int c = 0; c < 16; c++) fr[c] = fp[c];
    __syncthreads();

    float* Eb = g_E + (size_t)z * NE * NPTS + b;
#pragma unroll 1
    for (int n = 0; n < 48; n++) {
        const int ii = q * 48 + n;
        const float4* w = reinterpret_cast<const float4*>(s_wk + ii * 64);
        float a0 = 0.f, a1 = 0.f, a2 = 0.f, a3 = 0.f;
#pragma unroll
        for (int c = 0; c < 16; c++) {
            const float4 wv = w[c];
            a0 = fmaf(fr[c].x, wv.x, a0);
            a1 = fmaf(fr[c].y, wv.y, a1);
            a2 = fmaf(fr[c].z, wv.z, a2);
            a3 = fmaf(fr[c].w, wv.w, a3);
        }
        Eb[(size_t)ii * NPTS] = (a0 + a1) + (a2 + a3);
    }
}

// ---------------------------------------------------------------------------
// Prep 2: H[s][z][i'][b]. i'<64: c_b = sum_x g[b,x]*E[64x+i']; else E[i'-64].
// hi/lo bf16 split (hi = RN(v), lo = RN(v - hi)).
// ---------------------------------------------------------------------------
__global__ __launch_bounds__(256) void prep_h_kernel(const float* __restrict__ geom) {
    const int b  = blockIdx.x * 256 + threadIdx.x;
    const int z  = blockIdx.y >> 2;
    const int ig0 = (blockIdx.y & 3) * 64;
    const float* gp = geom + ((size_t)z * NPTS + b) * 3;
    const float g0 = gp[0], g1 = gp[1], g2 = gp[2];
    const float* Ez = g_E + (size_t)z * NE * NPTS;
    __nv_bfloat16* Hh = g_H + ((size_t)z * NIP) * NPTS;
    __nv_bfloat16* Hl = g_H + ((size_t)(BATCH + z) * NIP) * NPTS;
#pragma unroll 1
    for (int n = 0; n < 64; n++) {
        const int ip = ig0 + n;
        float v;
        if (ip < 64) {
            const float e0 = Ez[(size_t)ip * NPTS + b];
            const float e1 = Ez[(size_t)(64 + ip) * NPTS + b];
            const float e2 = Ez[(size_t)(128 + ip) * NPTS + b];
            v = fmaf(g0, e0, fmaf(g1, e1, g2 * e2));
        } else {
            v = Ez[(size_t)(ip - 64) * NPTS + b];
        }
        const __nv_bfloat16 hi = __float2bfloat16(v);
        const float lo = v - __bfloat162float(hi);
        Hh[(size_t)ip * NPTS + b] = hi;
        Hl[(size_t)ip * NPTS + b] = __float2bfloat16(lo);
    }
}

// ---------------------------------------------------------------------------
// Main: per CTA (z, 128 a-rows): P[128 x 256] = M @ (H_hi + H_lo) via
// mma.sync bf16, mask tile generated on CUDA cores per 64-b chunk.
// Epilogue: out[a,i] = P[a,i] - sum_x ga[x]*P[a,64+64x+i].
// ---------------------------------------------------------------------------
__global__ __launch_bounds__(THREADS, 1) void conv_mma_kernel(
    const float* __restrict__ geom, float* __restrict__ out)
{
    extern __shared__ __align__(16) char smem[];
    const uint32_t su = smem_u32(smem);

    const int z  = blockIdx.y;
    const int a0 = blockIdx.x * MT;
    const int t  = threadIdx.x;
    const int wid  = t >> 5, lane = t & 31;
    const int wm = wid >> 3, wn = wid & 7;        // warp tile: rows wm*64, cols wn*32
    const int m0 = wm * 64, n0 = wn * 32;
    const int fr = lane >> 2, fc = lane & 3;      // mma fragment row/col ids

    const float* gz = geom + (size_t)z * NPTS * 3;

    // ---- stage g_a as float4 ----
    if (t < MT) {
        const float* gp = gz + (size_t)(a0 + t) * 3;
        *reinterpret_cast<float4*>(smem + GA_OFF + t * 16) =
            make_float4(gp[0], gp[1], gp[2], 0.0f);
    }

    // ---- prologue: issue copies for chunk 0 ----
    {
#pragma unroll
        for (int it = 0; it < 8; it++) {
            const int m = t + THREADS * it;
            const int s = m >> 11, rem = m & 2047, row = rem >> 3, c16 = rem & 7;
            const __nv_bfloat16* src =
                g_H + (((size_t)(s * BATCH + z) * NIP + row) * NPTS + c16 * 8);
            cpasync16(su + B_OFF + (uint32_t)s * B_SPLIT + row * B_ROWB + c16 * 16, src);
        }
        if (t < 48)
            cpasync16(su + GBP_OFF + t * 16, (const char*)gz + t * 16);
        asm volatile("cp.async.commit_group;" ::: "memory");
    }
    __syncthreads();

    // mask-gen assignment: row rg = t/4, k-quarter qg = t&3
    const int rg = t >> 2, qg = t & 3;
    const float4 gaR = *reinterpret_cast<const float4*>(smem + GA_OFF + rg * 16);

    // accumulators
    float d[4][4][4];
#pragma unroll
    for (int mt = 0; mt < 4; mt++)
#pragma unroll
        for (int nt = 0; nt < 4; nt++)
#pragma unroll
            for (int r = 0; r < 4; r++) d[mt][nt][r] = 0.0f;

#pragma unroll 1
    for (int i = 0; i < NCHUNK; i++) {
        const uint32_t p = (uint32_t)(i & 1);

        __syncthreads();   // prior-stage reads complete before overwriting

        // ---- issue copies for chunk i+1 into stage p^1 ----
        if (i + 1 < NCHUNK) {
            const int b1 = (i + 1) * KC;
            const uint32_t bst = su + B_OFF + (p ^ 1u) * B_STAGE;
#pragma unroll
            for (int it = 0; it < 8; it++) {
                const int m = t + THREADS * it;
                const int s = m >> 11, rem = m & 2047, row = rem >> 3, c16 = rem & 7;
                const __nv_bfloat16* src =
                    g_H + (((size_t)(s * BATCH + z) * NIP + row) * NPTS + b1 + c16 * 8);
                cpasync16(bst + (uint32_t)s * B_SPLIT + row * B_ROWB + c16 * 16, src);
            }
            if (t < 48)
                cpasync16(su + GBP_OFF + (p ^ 1u) * 1024 + t * 16,
                          (const char*)(gz + (size_t)b1 * 3) + t * 16);
            asm volatile("cp.async.commit_group;" ::: "memory");
            asm volatile("cp.async.wait_group 1;" ::: "memory");
        } else {
            asm volatile("cp.async.wait_group 0;" ::: "memory");
        }

        // ---- convert packed gb -> float4 (swizzled slots: k + k/16) ----
        if (t < KC) {
            const float* gp = reinterpret_cast<const float*>(smem + GBP_OFF + p * 1024) + t * 3;
            const int slot = t + (t >> 4);
            *reinterpret_cast<float4*>(smem + GBQ_OFF + slot * 16) =
                make_float4(gp[0], gp[1], gp[2], 0.0f);
        }
        __syncthreads();

        // ---- generate mask tile A[128 x 64] bf16 into stage p ----
        {
            char* arow = smem + A_OFF + p * A_STAGE + rg * A_ROWB + qg * 32;
            const char* gbq = smem + GBQ_OFF;
#pragma unroll
            for (int u = 0; u < 8; u++) {
                const int k = qg * 16 + 2 * u;
                const float4 q0 = *reinterpret_cast<const float4*>(gbq + (k + (k >> 4)) * 16);
                const int k1 = k + 1;
                const float4 q1 = *reinterpret_cast<const float4*>(gbq + (k1 + (k1 >> 4)) * 16);
                const float dx0 = q0.x - gaR.x, dy0 = q0.y - gaR.y, dz0 = q0.z - gaR.z;
                const float dx1 = q1.x - gaR.x, dy1 = q1.y - gaR.y, dz1 = q1.z - gaR.z;
                const float nn0 = fmaf(dx0, dx0, fmaf(dy0, dy0, dz0 * dz0));
                const float nn1 = fmaf(dx1, dx1, fmaf(dy1, dy1, dz1 * dz1));
                const uint32_t v = (nn0 < 1.0f ? 0x3F80u : 0u)
                                 | (nn1 < 1.0f ? 0x3F800000u : 0u);
                *reinterpret_cast<uint32_t*>(arow + u * 4) = v;
            }
        }
        __syncthreads();

        // ---- fragment loads + 128 MMAs ----
        {
            const char* Ab = smem + A_OFF + p * A_STAGE + (m0 + fr) * A_ROWB + fc * 4;
            const char* Bb = smem + B_OFF + p * B_STAGE + (n0 + fr) * B_ROWB + fc * 4;
#pragma unroll
            for (int kk = 0; kk < 4; kk++) {
                uint32_t af[4][4];
#pragma unroll
                for (int mt = 0; mt < 4; mt++) {
                    const char* ap = Ab + mt * 16 * A_ROWB + kk * 32;
                    af[mt][0] = *reinterpret_cast<const uint32_t*>(ap);
                    af[mt][1] = *reinterpret_cast<const uint32_t*>(ap + 8 * A_ROWB);
                    af[mt][2] = *reinterpret_cast<const uint32_t*>(ap + 16);
                    af[mt][3] = *reinterpret_cast<const uint32_t*>(ap + 8 * A_ROWB + 16);
                }
#pragma unroll
                for (int s = 0; s < 2; s++) {
                    const char* Bs = Bb + s * B_SPLIT + kk * 32;
#pragma unroll
                    for (int nt = 0; nt < 4; nt++) {
                        const char* bp = Bs + nt * 8 * B_ROWB;
                        const uint32_t b0 = *reinterpret_cast<const uint32_t*>(bp);
                        const uint32_t b1 = *reinterpret_cast<const uint32_t*>(bp + 16);
#pragma unroll
                        for (int mt = 0; mt < 4; mt++)
                            mma16816(d[mt][nt][0], d[mt][nt][1], d[mt][nt][2], d[mt][nt][3],
                                     af[mt][0], af[mt][1], af[mt][2], af[mt][3], b0, b1);
                    }
                }
            }
        }
    }

    // ---- epilogue: P -> smem (reuse A/B region), combine, store ----
    __syncthreads();
    float* P = reinterpret_cast<float*>(smem);   // [128][260] floats
#pragma unroll
    for (int mt = 0; mt < 4; mt++) {
#pragma unroll
        for (int nt = 0; nt < 4; nt++) {
            const int R0 = m0 + mt * 16 + fr;
            const int C  = n0 + nt * 8 + 2 * fc;
            *reinterpret_cast<float2*>(P + R0 * 260 + C)       = make_float2(d[mt][nt][0], d[mt][nt][1]);
            *reinterpret_cast<float2*>(P + (R0 + 8) * 260 + C) = make_float2(d[mt][nt][2], d[mt][nt][3]);
        }
    }
    __syncthreads();

    {
        const int al = t >> 2, iq = t & 3;
        const float4 ga4 = *reinterpret_cast<const float4*>(smem + GA_OFF + al * 16);
        float* orow = out + ((size_t)z * NPTS + a0 + al) * 64;
        const float* Pr = P + al * 260;
#pragma unroll
        for (int jj = 0; jj < 4; jj++) {
            const int i0 = iq * 4 + jj * 16;
            const float4 vc = *reinterpret_cast<const float4*>(Pr + i0);
            const float4 v1 = *reinterpret_cast<const float4*>(Pr + 64 + i0);
            const float4 v2 = *reinterpret_cast<const float4*>(Pr + 128 + i0);
            const float4 v3 = *reinterpret_cast<const float4*>(Pr + 192 + i0);
            float4 o;
            o.x = fmaf(-ga4.z, v3.x, fmaf(-ga4.y, v2.x, fmaf(-ga4.x, v1.x, vc.x)));
            o.y = fmaf(-ga4.z, v3.y, fmaf(-ga4.y, v2.y, fmaf(-ga4.x, v1.y, vc.y)));
            o.z = fmaf(-ga4.z, v3.z, fmaf(-ga4.y, v2.z, fmaf(-ga4.x, v1.z, vc.z)));
            o.w = fmaf(-ga4.z, v3.w, fmaf(-ga4.y, v2.w, fmaf(-ga4.x, v1.w, vc.w)));
            *reinterpret_cast<float4*>(orow + i0) = o;
        }
    }
}

// ---------------------------------------------------------------------------
// Launcher. Inputs: features [8,2048,64] f32, geometry [8,2048,3] f32,
// Wk [3,64,64] f32. Output [8,2048,64] f32.
// ---------------------------------------------------------------------------
extern "C" void kernel_launch(void* const* d_in, const int* in_sizes, int n_in,
                              void* d_out, int out_size) {
    const float* feat = (const float*)d_in[0];
    const float* geom = (const float*)d_in[1];
    const float* Wk   = (const float*)d_in[2];
    float* out = (float*)d_out;
    (void)in_sizes; (void)n_in; (void)out_size;

    cudaFuncSetAttribute(conv_mma_kernel,
                         cudaFuncAttributeMaxDynamicSharedMemorySize, SMEM_BYTES);

    prep_e_kernel<<<dim3(NPTS / 64, BATCH), 256>>>(feat, Wk);
    prep_h_kernel<<<dim3(NPTS / 256, BATCH * 4), 256>>>(geom);
    conv_mma_kernel<<<dim3(NPTS / MT, BATCH), THREADS, SMEM_BYTES>>>(geom, out);
}

// round 6
// speedup vs baseline: 2.2640x; 1.0475x over previous
#include <cuda_runtime.h>
#include <cuda_bf16.h>
#include <cstdint>

#define BATCH 8
#define NPTS  2048
#define CIN   64
#define NE    192            // e rows (3*64)
#define NIP   256            // H width: [c(64) | e(192)]
#define MT    128            // a-rows per CTA
#define KC    64             // K chunk (b's)
#define NCHUNK (NPTS / KC)
#define THREADS 256

// Static device scratch (allocation is forbidden)
__device__ float g_E[(size_t)BATCH * NE * NPTS];                             // [z][i''][b]
__device__ __align__(128) __nv_bfloat16 g_H[(size_t)2 * BATCH * NIP * NPTS]; // [s][z][i'][b]

// ---------------- smem layout (byte offsets) ----------------
#define A_ROWB   144u
#define A_STAGE  (MT * A_ROWB)        // 18432
#define A_OFF    0u                   // 2 stages: 36864
#define B_ROWB   144u
#define B_SPLIT  (NIP * B_ROWB)       // 36864
#define B_STAGE  (2u * B_SPLIT)       // 73728 (hi+lo)
#define B_OFF    36864u               // 2 stages -> 184320
#define GBP_OFF  184320u              // packed gb, 2 stages x 1024
#define GBQ_OFF  186368u              // float4 gb (swizzled slots), 1088
#define GA_OFF   187456u              // 128 x float4
#define SMEM_BYTES (GA_OFF + 2048u)   // 189504

__device__ __forceinline__ uint32_t smem_u32(const void* p) {
    uint32_t a;
    asm("{ .reg .u64 t; cvta.to.shared.u64 t, %1; cvt.u32.u64 %0, t; }" : "=r"(a) : "l"(p));
    return a;
}
__device__ __forceinline__ void cpasync16(uint32_t dst, const void* src) {
    asm volatile("cp.async.cg.shared.global [%0], [%1], 16;" :: "r"(dst), "l"(src) : "memory");
}
__device__ __forceinline__ void ldsm_x4(uint32_t& r0, uint32_t& r1, uint32_t& r2, uint32_t& r3,
                                        uint32_t addr) {
    asm volatile("ldmatrix.sync.aligned.m8n8.x4.shared.b16 {%0,%1,%2,%3}, [%4];"
                 : "=r"(r0), "=r"(r1), "=r"(r2), "=r"(r3) : "r"(addr));
}
__device__ __forceinline__ void mma16816(float& d0, float& d1, float& d2, float& d3,
                                         uint32_t a0, uint32_t a1, uint32_t a2, uint32_t a3,
                                         uint32_t b0, uint32_t b1) {
    asm volatile(
        "mma.sync.aligned.m16n8k16.row.col.f32.bf16.bf16.f32 "
        "{%0,%1,%2,%3}, {%4,%5,%6,%7}, {%8,%9}, {%0,%1,%2,%3};"
        : "+f"(d0), "+f"(d1), "+f"(d2), "+f"(d3)
        : "r"(a0), "r"(a1), "r"(a2), "r"(a3), "r"(b0), "r"(b1));
}

// ---------------------------------------------------------------------------
// Prep 1: E[z][i''][b] = sum_j feat[z][b][j] * Wk[x][i][j], i'' = 64x + i.
// 512 blocks (b-tile 32, 8 i-groups of 24) for occupancy.
// ---------------------------------------------------------------------------
__global__ __launch_bounds__(256) void prep_e_kernel(const float* __restrict__ feat,
                                                     const float* __restrict__ Wk) {
    __shared__ float s_wk[3 * 64 * 64];   // 48 KB
    const int z  = blockIdx.y;
    const int b0 = blockIdx.x * 32;
    const int t  = threadIdx.x;
    for (int m = t; m < 3 * 64 * 64 / 4; m += 256)
        reinterpret_cast<float4*>(s_wk)[m] = reinterpret_cast<const float4*>(Wk)[m];

    const int bl = t & 31, q = t >> 5;
    const int b = b0 + bl;
    float4 fr[16];
    const float4* fp = reinterpret_cast<const float4*>(feat + ((size_t)z * NPTS + b) * CIN);
#pragma unroll
    for (int c = 0; c < 16; c++) fr[c] = fp[c];
    __syncthreads();

    float* Eb = g_E + (size_t)z * NE * NPTS + b;
#pragma unroll 1
    for (int n = 0; n < 24; n++) {
        const int ii = q * 24 + n;
        const float4* w = reinterpret_cast<const float4*>(s_wk + ii * 64);
        float a0 = 0.f, a1 = 0.f, a2 = 0.f, a3 = 0.f;
#pragma unroll
        for (int c = 0; c < 16; c++) {
            const float4 wv = w[c];
            a0 = fmaf(fr[c].x, wv.x, a0);
            a1 = fmaf(fr[c].y, wv.y, a1);
            a2 = fmaf(fr[c].z, wv.z, a2);
            a3 = fmaf(fr[c].w, wv.w, a3);
        }
        Eb[(size_t)ii * NPTS] = (a0 + a1) + (a2 + a3);
    }
}

// ---------------------------------------------------------------------------
// Prep 2: H[s][z][i'][b]. i'<64: c_b = sum_x g[b,x]*E[64x+i']; else E[i'-64].
// hi/lo bf16 split; 2 b's per thread -> packed u32 stores.
// ---------------------------------------------------------------------------
__global__ __launch_bounds__(128) void prep_h_kernel(const float* __restrict__ geom) {
    const int b   = (blockIdx.x * 128 + threadIdx.x) * 2;
    const int z   = blockIdx.y >> 2;
    const int ig0 = (blockIdx.y & 3) * 64;
    const float* gp0 = geom + ((size_t)z * NPTS + b) * 3;
    const float g00 = gp0[0], g01 = gp0[1], g02 = gp0[2];
    const float g10 = gp0[3], g11 = gp0[4], g12 = gp0[5];
    const float* Ez = g_E + (size_t)z * NE * NPTS;
    uint32_t* Hh = reinterpret_cast<uint32_t*>(g_H + ((size_t)z * NIP) * NPTS);
    uint32_t* Hl = reinterpret_cast<uint32_t*>(g_H + ((size_t)(BATCH + z) * NIP) * NPTS);
#pragma unroll 1
    for (int n = 0; n < 64; n++) {
        const int ip = ig0 + n;
        float v0, v1;
        if (ip < 64) {
            const float2 e0 = *reinterpret_cast<const float2*>(Ez + (size_t)ip * NPTS + b);
            const float2 e1 = *reinterpret_cast<const float2*>(Ez + (size_t)(64 + ip) * NPTS + b);
            const float2 e2 = *reinterpret_cast<const float2*>(Ez + (size_t)(128 + ip) * NPTS + b);
            v0 = fmaf(g00, e0.x, fmaf(g01, e1.x, g02 * e2.x));
            v1 = fmaf(g10, e0.y, fmaf(g11, e1.y, g12 * e2.y));
        } else {
            const float2 e = *reinterpret_cast<const float2*>(Ez + (size_t)(ip - 64) * NPTS + b);
            v0 = e.x; v1 = e.y;
        }
        const __nv_bfloat16 h0 = __float2bfloat16(v0);
        const __nv_bfloat16 h1 = __float2bfloat16(v1);
        const __nv_bfloat16 l0 = __float2bfloat16(v0 - __bfloat162float(h0));
        const __nv_bfloat16 l1 = __float2bfloat16(v1 - __bfloat162float(h1));
        const size_t idx = ((size_t)ip * NPTS + b) >> 1;
        Hh[idx] = (uint32_t)__bfloat16_as_ushort(h0) | ((uint32_t)__bfloat16_as_ushort(h1) << 16);
        Hl[idx] = (uint32_t)__bfloat16_as_ushort(l0) | ((uint32_t)__bfloat16_as_ushort(l1) << 16);
    }
}

// ---------------------------------------------------------------------------
// Main: per CTA (z, 128 a-rows): P[128 x 256] = M @ (H_hi + H_lo) via
// mma.sync bf16 (ldmatrix fragments), mask tile generated per 64-b chunk.
// 8 warps, warp tile 64x64. Epilogue: out = P_c - sum_x ga[x]*P_e[x].
// ---------------------------------------------------------------------------
__global__ __launch_bounds__(THREADS, 1) void conv_mma_kernel(
    const float* __restrict__ geom, float* __restrict__ out)
{
    extern __shared__ __align__(16) char smem[];
    const uint32_t su = smem_u32(smem);

    const int z  = blockIdx.y;
    const int a0 = blockIdx.x * MT;
    const int t  = threadIdx.x;
    const int wid = t >> 5, lane = t & 31;
    const int m0 = (wid >> 2) * 64, n0 = (wid & 3) * 64;
    const int fr = lane >> 2, fc = lane & 3;

    const float* gz = geom + (size_t)z * NPTS * 3;

    // ---- stage g_a as float4 ----
    if (t < MT) {
        const float* gp = gz + (size_t)(a0 + t) * 3;
        *reinterpret_cast<float4*>(smem + GA_OFF + t * 16) =
            make_float4(gp[0], gp[1], gp[2], 0.0f);
    }

    // ---- prologue: copies for chunk 0 (stage 0) ----
#pragma unroll
    for (int it = 0; it < 16; it++) {
        const int m = t + THREADS * it;
        const int s = m >> 11, rem = m & 2047, row = rem >> 3, c16 = rem & 7;
        const __nv_bfloat16* src =
            g_H + (((size_t)(s * BATCH + z) * NIP + row) * NPTS + c16 * 8);
        cpasync16(su + B_OFF + (uint32_t)s * B_SPLIT + row * B_ROWB + c16 * 16, src);
    }
    if (t < 48) cpasync16(su + GBP_OFF + t * 16, (const char*)gz + t * 16);
    asm volatile("cp.async.commit_group;" ::: "memory");
    __syncthreads();

    // mask-gen assignment: row rg, k-half hg
    const int rg = t >> 1, hg = t & 1;
    const float4 gaR = *reinterpret_cast<const float4*>(smem + GA_OFF + rg * 16);

    // ldmatrix per-lane base addresses
    const uint32_t aLane = (uint32_t)((m0 + ((lane >> 3) & 1) * 8 + (lane & 7)) * A_ROWB
                                      + (lane >> 4) * 16);
    const uint32_t bLane = (uint32_t)((n0 + (lane >> 4) * 8 + (lane & 7)) * B_ROWB
                                      + ((lane >> 3) & 1) * 16);

    float d[4][8][4];
#pragma unroll
    for (int mt = 0; mt < 4; mt++)
#pragma unroll
        for (int nt = 0; nt < 8; nt++)
#pragma unroll
            for (int r = 0; r < 4; r++) d[mt][nt][r] = 0.0f;

#pragma unroll 1
    for (int i = 0; i < NCHUNK; i++) {
        const uint32_t p = (uint32_t)(i & 1);

        __syncthreads();   // all MMA reads of stage p^1 (chunk i-1) complete

        if (i + 1 < NCHUNK) {
            const int b1 = (i + 1) * KC;
            const uint32_t bst = su + B_OFF + (p ^ 1u) * B_STAGE;
#pragma unroll
            for (int it = 0; it < 16; it++) {
                const int m = t + THREADS * it;
                const int s = m >> 11, rem = m & 2047, row = rem >> 3, c16 = rem & 7;
                const __nv_bfloat16* src =
                    g_H + (((size_t)(s * BATCH + z) * NIP + row) * NPTS + b1 + c16 * 8);
                cpasync16(bst + (uint32_t)s * B_SPLIT + row * B_ROWB + c16 * 16, src);
            }
            if (t < 48)
                cpasync16(su + GBP_OFF + (p ^ 1u) * 1024 + t * 16,
                          (const char*)(gz + (size_t)b1 * 3) + t * 16);
            asm volatile("cp.async.commit_group;" ::: "memory");
            asm volatile("cp.async.wait_group 1;" ::: "memory");
        } else {
            asm volatile("cp.async.wait_group 0;" ::: "memory");
        }

        // ---- convert packed gb -> float4 (swizzled slots: k + k/16) ----
        if (t < KC) {
            const float* gp = reinterpret_cast<const float*>(smem + GBP_OFF + p * 1024) + t * 3;
            const int slot = t + (t >> 4);
            *reinterpret_cast<float4*>(smem + GBQ_OFF + slot * 16) =
                make_float4(gp[0], gp[1], gp[2], 0.0f);
        }
        __syncthreads();

        // ---- generate mask tile A[128 x 64] bf16 into stage p ----
        {
            char* arow = smem + A_OFF + p * A_STAGE + rg * A_ROWB + hg * 64;
            const char* gbq = smem + GBQ_OFF;
#pragma unroll
            for (int u = 0; u < 16; u++) {
                const int k = hg * 32 + 2 * u;
                const float4 q0 = *reinterpret_cast<const float4*>(gbq + (k + (k >> 4)) * 16);
                const int k1 = k + 1;
                const float4 q1 = *reinterpret_cast<const float4*>(gbq + (k1 + (k1 >> 4)) * 16);
                const float dx0 = q0.x - gaR.x, dy0 = q0.y - gaR.y, dz0 = q0.z - gaR.z;
                const float dx1 = q1.x - gaR.x, dy1 = q1.y - gaR.y, dz1 = q1.z - gaR.z;
                const float nn0 = fmaf(dx0, dx0, fmaf(dy0, dy0, dz0 * dz0));
                const float nn1 = fmaf(dx1, dx1, fmaf(dy1, dy1, dz1 * dz1));
                const uint32_t v = (nn0 < 1.0f ? 0x3F80u : 0u)
                                 | (nn1 < 1.0f ? 0x3F800000u : 0u);
                *reinterpret_cast<uint32_t*>(arow + u * 4) = v;
            }
        }
        __syncthreads();

        // ---- ldmatrix fragments + 256 MMAs per warp ----
        {
            const uint32_t Ab = su + A_OFF + p * A_STAGE + aLane;
            const uint32_t Bb = su + B_OFF + p * B_STAGE + bLane;
#pragma unroll
            for (int kk = 0; kk < 4; kk++) {
                uint32_t af[4][4];
#pragma unroll
                for (int mt = 0; mt < 4; mt++)
                    ldsm_x4(af[mt][0], af[mt][1], af[mt][2], af[mt][3],
                            Ab + (uint32_t)(mt * 16 * A_ROWB + kk * 32));
#pragma unroll
                for (int s = 0; s < 2; s++) {
#pragma unroll
                    for (int ntp = 0; ntp < 4; ntp++) {
                        uint32_t b0, b1, b2, b3;
                        ldsm_x4(b0, b1, b2, b3,
                                Bb + (uint32_t)(s * B_SPLIT + ntp * 16 * B_ROWB + kk * 32));
#pragma unroll
                        for (int mt = 0; mt < 4; mt++) {
                            mma16816(d[mt][2*ntp][0], d[mt][2*ntp][1], d[mt][2*ntp][2], d[mt][2*ntp][3],
                                     af[mt][0], af[mt][1], af[mt][2], af[mt][3], b0, b1);
                            mma16816(d[mt][2*ntp+1][0], d[mt][2*ntp+1][1], d[mt][2*ntp+1][2], d[mt][2*ntp+1][3],
                                     af[mt][0], af[mt][1], af[mt][2], af[mt][3], b2, b3);
                        }
                    }
                }
            }
        }
    }

    // ---- epilogue: P -> smem (reuse A/B region), combine, store ----
    __syncthreads();
    float* P = reinterpret_cast<float*>(smem);   // [128][260]
#pragma unroll
    for (int mt = 0; mt < 4; mt++) {
#pragma unroll
        for (int nt = 0; nt < 8; nt++) {
            const int R0 = m0 + mt * 16 + fr;
            const int C  = n0 + nt * 8 + 2 * fc;
            *reinterpret_cast<float2*>(P + R0 * 260 + C)       = make_float2(d[mt][nt][0], d[mt][nt][1]);
            *reinterpret_cast<float2*>(P + (R0 + 8) * 260 + C) = make_float2(d[mt][nt][2], d[mt][nt][3]);
        }
    }
    __syncthreads();

    {
        const int al = t >> 1, iq = t & 1;
        const float4 ga4 = *reinterpret_cast<const float4*>(smem + GA_OFF + al * 16);
        float* orow = out + ((size_t)z * NPTS + a0 + al) * 64;
        const float* Pr = P + al * 260;
#pragma unroll
        for (int w = 0; w < 8; w++) {
            const int i0 = iq * 32 + w * 4;
            const float4 vc = *reinterpret_cast<const float4*>(Pr + i0);
            const float4 v1 = *reinterpret_cast<const float4*>(Pr + 64 + i0);
            const float4 v2 = *reinterpret_cast<const float4*>(Pr + 128 + i0);
            const float4 v3 = *reinterpret_cast<const float4*>(Pr + 192 + i0);
            float4 o;
            o.x = fmaf(-ga4.z, v3.x, fmaf(-ga4.y, v2.x, fmaf(-ga4.x, v1.x, vc.x)));
            o.y = fmaf(-ga4.z, v3.y, fmaf(-ga4.y, v2.y, fmaf(-ga4.x, v1.y, vc.y)));
            o.z = fmaf(-ga4.z, v3.z, fmaf(-ga4.y, v2.z, fmaf(-ga4.x, v1.z, vc.z)));
            o.w = fmaf(-ga4.z, v3.w, fmaf(-ga4.y, v2.w, fmaf(-ga4.x, v1.w, vc.w)));
            *reinterpret_cast<float4*>(orow + i0) = o;
        }
    }
}

// ---------------------------------------------------------------------------
// Launcher. Inputs: features [8,2048,64] f32, geometry [8,2048,3] f32,
// Wk [3,64,64] f32. Output [8,2048,64] f32.
// ---------------------------------------------------------------------------
extern "C" void kernel_launch(void* const* d_in, const int* in_sizes, int n_in,
                              void* d_out, int out_size) {
    const float* feat = (const float*)d_in[0];
    const float* geom = (const float*)d_in[1];
    const float* Wk   = (const float*)d_in[2];
    float* out = (float*)d_out;
    (void)in_sizes; (void)n_in; (void)out_size;

    cudaFuncSetAttribute(conv_mma_kernel,
                         cudaFuncAttributeMaxDynamicSharedMemorySize, SMEM_BYTES);

    prep_e_kernel<<<dim3(NPTS / 32, BATCH), 256>>>(feat, Wk);
    prep_h_kernel<<<dim3(NPTS / 256, BATCH * 4), 128>>>(geom);
    conv_mma_kernel<<<dim3(NPTS / MT, BATCH), THREADS, SMEM_BYTES>>>(geom, out);
}